// round 1
// baseline (speedup 1.0000x reference)
#include <cuda_runtime.h>
#include <cstdint>

#define HH 10
#define WW 10
#define TPB 64

// two uint64 words, rows 0-4 in w0, rows 5-9 in w1, 12-bit row pitch (bits 10,11 guard)
#define COLM 0x03FF3FF3FF3FF3FFull

__device__ double g_partials[8192];

__global__ __launch_bounds__(TPB) void loss_kernel(const float* __restrict__ res,
                                                   const int* __restrict__ pts,
                                                   int B) {
    __shared__ float s[TPB * 100];
    const int t = threadIdx.x;
    const int warp = t >> 5, lane = t & 31;
    const long long blockSample = (long long)blockIdx.x * TPB;
    const long long warpSample = blockSample + warp * 32;

    // ---- cooperative staging: warp loads its 32 samples (800 float4, coalesced) ----
    {
        long long rem = B - warpSample;
        const float4* gsrc = (const float4*)(res + warpSample * 100);
        float4* sdst = (float4*)(s + warp * 32 * 100);
        if (rem >= 32) {
#pragma unroll
            for (int i = 0; i < 25; i++)
                sdst[i * 32 + lane] = gsrc[i * 32 + lane];
        } else if (rem > 0) {
            int n4 = (int)rem * 25;
            for (int i = lane; i < n4; i += 32) sdst[i] = gsrc[i];
        }
    }
    __syncwarp();

    float loss = 0.0f;
    const long long sample = blockSample + t;
    if (sample < B) {
        const float* r = s + t * 100;
        const int4 p = ((const int4*)pts)[sample];
        const int p0y = p.x, p0x = p.y, p1y = p.z, p1x = p.w;
        const int ady = abs(p0y - p1y), adx = abs(p0x - p1x);
        const int base = ady + adx;

        // 0.5 * per-axis detour
        float dyh[HH], dxh[WW];
#pragma unroll
        for (int i = 0; i < 10; i++) {
            dyh[i] = 0.5f * (float)(abs(i - p0y) + abs(i - p1y) - ady);
            dxh[i] = 0.5f * (float)(abs(i - p0x) + abs(i - p1x) - adx);
        }

        // ---- pass 1: S, single_cell, lit-mask bits ----
        float S = 0.0f, sc = 0.0f;
        unsigned long long m0 = 0ull, m1 = 0ull;
        const float4* rp4 = (const float4*)r;
#pragma unroll
        for (int c4 = 0; c4 < 25; c4++) {
            float4 v = rp4[c4];
            float vv[4] = {v.x, v.y, v.z, v.w};
#pragma unroll
            for (int k = 0; k < 4; k++) {
                const int f = c4 * 4 + k;
                const int y = f / 10, x = f % 10;
                const float val = vv[k];
                S += val;
                if (val > 0.5f) {   // exactly rint(val)==1 for val in [0,1)
                    if (y < 5) m0 |= 1ull << (y * 12 + x);
                    else       m1 |= 1ull << ((y - 5) * 12 + x);
                }
                const float dh = dyh[y] + dxh[x];           // 0.5*delta (exact)
                const float a = fmaf(-20.0f, val, 20.0f);   // (1-r)*20
                const float b = val * dh;                   // r*delta*0.5
                sc += (dh == 0.0f) ? a : b;
            }
        }

        // ---- bit-parallel 8-connected flood fill from p0 (<=20 dilations) ----
        unsigned long long c0 = 0ull, c1 = 0ull;
        if (p0y < 5) c0 = 1ull << (p0y * 12 + p0x);
        else         c1 = 1ull << ((p0y - 5) * 12 + p0x);
#pragma unroll 1
        for (int it = 0; it < 20; it++) {
            const unsigned long long s0 = (c0 | (c0 << 1) | (c0 >> 1)) & COLM;
            const unsigned long long s1 = (c1 | (c1 << 1) | (c1 >> 1)) & COLM;
            // self bits in nb are harmless: they are already in c
            const unsigned long long nb0 = s0 | (s0 << 12) | (s0 >> 12) | (s1 << 48);
            const unsigned long long nb1 = s1 | (s1 << 12) | (s1 >> 12) | (s0 >> 48);
            const unsigned long long n0 = c0 | (nb0 & m0);
            const unsigned long long n1 = c1 | (nb1 & m1);
            if (n0 == c0 && n1 == c1) break;
            c0 = n0; c1 = n1;
        }
        const int csize = __popcll(c0) + __popcll(c1);

        // per-row cluster bits
        unsigned cl[HH];
#pragma unroll
        for (int y = 0; y < 10; y++)
            cl[y] = (unsigned)((y < 5 ? (c0 >> (12 * y)) : (c1 >> (12 * (y - 5)))) & 0x3FFu);

        // ---- pass 2: S_cl over transposed cluster membership ----
        float Scl = 0.0f;
#pragma unroll
        for (int c4 = 0; c4 < 25; c4++) {
            float4 v = rp4[c4];
            float vv[4] = {v.x, v.y, v.z, v.w};
#pragma unroll
            for (int k = 0; k < 4; k++) {
                const int f = c4 * 4 + k;
                const int y = f / 10, x = f % 10;
                if ((cl[x] >> y) & 1u) Scl += vv[k];
            }
        }

        // ---- argmin over cluster of dist-to-end (first flat index on ties) ----
        int minv = HH * WW + 10, bny = p0y, bnx = p0x;
#pragma unroll
        for (int y = 0; y < 10; y++) {
            const unsigned bits = cl[y];
            if (!bits) continue;
            const int dy = abs(y - p1y);
            const unsigned left = bits & ((2u << p1x) - 1u);
            const unsigned right = bits & (0xFFFFFFFFu << p1x);
            if (left) {            // nearest set bit at x <= p1x (smaller x first)
                const int xl = 31 - __clz(left);
                const int d = dy + (p1x - xl);
                if (d < minv) { minv = d; bny = y; bnx = xl; }
            }
            if (right) {           // nearest set bit at x >= p1x
                const int xr = __ffs(right) - 1;
                const int d = dy + (xr - p1x);
                if (d < minv) { minv = d; bny = y; bnx = xr; }
            }
        }
        const bool better = minv < base;
        const int ny = better ? bny : p0y;
        const int nx = better ? bnx : p0x;
        const int gap = min(base, minv);

        // ---- neighbor-toward-end cascade ----
        int by = ny, bx = nx, bg = gap;
        const int oy = p1y - ny, ox = p1x - nx;
#define UPD(cond, cy, cx) do { \
            const int _cy = (cy), _cx = (cx); \
            const int _d = abs(_cy - p1y) + abs(_cx - p1x); \
            if ((cond) && _d < bg) { by = _cy; bx = _cx; bg = _d; } \
        } while (0)
        UPD(ox < 0, ny, nx - 1);
        UPD(ox < 0 && ny != 0, ny - 1, nx - 1);
        UPD(ox < 0 && ny != HH - 1, ny + 1, nx - 1);
        UPD(ox > 0, ny, nx + 1);
        UPD(ox > 0 && ny != 0, ny - 1, nx + 1);
        UPD(ox > 0 && ny != HH - 1, ny + 1, nx + 1);
        UPD(oy < 0, ny - 1, nx);
        UPD(oy > 0, ny + 1, nx);
#undef UPD
        const int ncy = min(max(by, 0), HH - 1);
        const int ncx = min(max(bx, 0), WW - 1);

        // ---- assemble ----
        const float r0 = r[p0y * 10 + p0x];
        const float r1 = r[p1y * 10 + p1x];
        const float csz = (float)csize;
        const float loss_start = (2.0f - (r0 + r1)) * 1000.0f;
        const float lonely = 15.0f * S + 5.0f * csz - 20.0f * Scl;
        const float cpen = 12.0f * csz * Scl;
        const float gpen = (float)gap * 300.0f * (1.0f - r[ncy * 10 + ncx]);
        loss = loss_start + lonely + sc + cpen + gpen;
    }

    // ---- block reduction -> double partial ----
    float l = loss;
#pragma unroll
    for (int o = 16; o; o >>= 1) l += __shfl_xor_sync(0xFFFFFFFFu, l, o);
    __shared__ float wsum[TPB / 32];
    if (lane == 0) wsum[warp] = l;
    __syncthreads();
    if (t == 0) {
        double acc = 0.0;
#pragma unroll
        for (int w = 0; w < TPB / 32; w++) acc += (double)wsum[w];
        g_partials[blockIdx.x] = acc;
    }
}

__global__ void reduce_kernel(float* __restrict__ out, int n) {
    __shared__ double sh[32];
    double a = 0.0;
    for (int i = threadIdx.x; i < n; i += blockDim.x) a += g_partials[i];
#pragma unroll
    for (int o = 16; o; o >>= 1) a += __shfl_xor_sync(0xFFFFFFFFu, a, o);
    const int wid = threadIdx.x >> 5;
    if ((threadIdx.x & 31) == 0) sh[wid] = a;
    __syncthreads();
    if (threadIdx.x < 32) {
        double b = (threadIdx.x < (blockDim.x >> 5)) ? sh[threadIdx.x] : 0.0;
#pragma unroll
        for (int o = 16; o; o >>= 1) b += __shfl_xor_sync(0xFFFFFFFFu, b, o);
        if (threadIdx.x == 0) out[0] = (float)b;
    }
}

extern "C" void kernel_launch(void* const* d_in, const int* in_sizes, int n_in,
                              void* d_out, int out_size) {
    const float* res = (const float*)d_in[0];
    const int* pts = (const int*)d_in[1];
    const int B = in_sizes[0] / 100;
    const int nblk = (B + TPB - 1) / TPB;   // 4096 for B=262144
    loss_kernel<<<nblk, TPB>>>(res, pts, B);
    reduce_kernel<<<1, 256>>>((float*)d_out, nblk);
}